// round 16
// baseline (speedup 1.0000x reference)
#include <cuda_runtime.h>
#include <cuda_fp16.h>
#include <cstdint>

// ============================================================================
// NestedMoEModel: softmax gate row-sums to 1 => gate path is a no-op.
// out[B, G*H] = x @ (sum_e W_exp)^T + sum_e b_exp
// Single GEMM M=32768, N=2048, K=256 via fp16 mma.sync (fp32 accumulate).
// PTX target is sm_103 (no 'a') -> tcgen05 unavailable; mma.sync path.
// R16: prep fused INTO the gemm kernel with producer->consumer flags:
//      grid = [1024 W-prep][per mtile: 8 X-prep, 16 gemm]. X conversion
//      overlaps the GEMM mainloop instead of serializing in front of it.
//      Deadlock-free: every gemm block's spin targets precede it in the grid
//      and prep blocks never wait. gemm body = R15 verbatim (97us, at the
//      legacy mma.sync issue ceiling).
// ============================================================================

#define DINLINE __device__ __forceinline__

static constexpr int Bsz = 32768;
static constexpr int Dsz = 256;     // K
static constexpr int NN  = 2048;    // G*H = output cols
static constexpr int M_TILE = 128;
static constexpr int N_TILE = 128;
static constexpr int K_CHUNK = 64;                   // halves per chunk (128B rows)
static constexpr int NUM_CHUNKS = Dsz / K_CHUNK;     // 4
static constexpr int STAGES = 3;
static constexpr int THREADS = 128;                  // 4 warps, 2x2 grid of 64x64

static constexpr int NUM_MTILES = Bsz / M_TILE;      // 256
static constexpr int NUM_NTILES = NN / N_TILE;       // 16
static constexpr int NW_BLOCKS  = 1024;              // W-prep blocks
static constexpr int X_PER_M    = 8;                 // X-prep blocks per mtile
static constexpr int GRP        = X_PER_M + NUM_NTILES;      // 24
static constexpr int GRID_TOTAL = NW_BLOCKS + NUM_MTILES * GRP;  // 7168

// SMEM: 3 stages, each A(16KB)+B(16KB), + bias
static constexpr int A_BYTES = M_TILE * 128;         // 16384
static constexpr int B_BYTES = N_TILE * 128;         // 16384
static constexpr int STAGE_BYTES = A_BYTES + B_BYTES;    // 32768
static constexpr int OFF_BIAS = STAGES * STAGE_BYTES;    // 98304
static constexpr int SMEM_TOTAL = OFF_BIAS + N_TILE * 4; // 98816 -> 2 CTAs/SM

// Scratch (device globals: no allocations allowed)
__device__ __align__(128) __half g_Wh[NN * Dsz];     // 1MB  fp16 reduced weights
__device__ __align__(128) __half g_Xh[Bsz * Dsz];    // 16MB fp16 x
__device__ __align__(128) float  g_bsum[NN];
// [0] = W-prep completion count (target 1024); [1+m] = xcnt (target 8)
__device__ int g_cnt[1 + NUM_MTILES];

// ---------------------------------------------------------------------------
// helpers
// ---------------------------------------------------------------------------
DINLINE uint32_t smem_u32(const void* p) {
    uint32_t a;
    asm("{ .reg .u64 t; cvta.to.shared.u64 t, %1; cvt.u32.u64 %0, t; }"
        : "=r"(a) : "l"(p));
    return a;
}

DINLINE void cp_async16(uint32_t saddr, const void* gaddr) {
    asm volatile("cp.async.cg.shared.global [%0], [%1], 16;"
                 :: "r"(saddr), "l"(gaddr) : "memory");
}
#define CP_COMMIT() asm volatile("cp.async.commit_group;" ::: "memory")
#define CP_WAIT(n)  asm volatile("cp.async.wait_group %0;" :: "n"(n) : "memory")

// SW128-style XOR swizzle for 128B rows (16B granularity)
#define SWZ(o) ((o) ^ (((o) >> 3) & 0x70))

DINLINE void ldsm_x4(uint32_t& r0, uint32_t& r1, uint32_t& r2, uint32_t& r3,
                     uint32_t addr) {
    asm volatile("ldmatrix.sync.aligned.m8n8.x4.shared.b16 {%0,%1,%2,%3}, [%4];"
                 : "=r"(r0), "=r"(r1), "=r"(r2), "=r"(r3) : "r"(addr));
}

DINLINE void mma16816(float* d, const uint32_t* a, const uint32_t* b) {
    asm volatile(
        "mma.sync.aligned.m16n8k16.row.col.f32.f16.f16.f32 "
        "{%0,%1,%2,%3}, {%4,%5,%6,%7}, {%8,%9}, {%0,%1,%2,%3};"
        : "+f"(d[0]), "+f"(d[1]), "+f"(d[2]), "+f"(d[3])
        : "r"(a[0]), "r"(a[1]), "r"(a[2]), "r"(a[3]), "r"(b[0]), "r"(b[1]));
}

// read-once fp32 sources: streaming loads (evict-first in L2)
DINLINE float2 ldcs_f2(const float* p) {
    float2 v;
    asm("ld.global.cs.v2.f32 {%0, %1}, [%2];"
        : "=f"(v.x), "=f"(v.y) : "l"(p));
    return v;
}
DINLINE float4 ldcs_f4(const float* p) {
    float4 v;
    asm("ld.global.cs.v4.f32 {%0, %1, %2, %3}, [%4];"
        : "=f"(v.x), "=f"(v.y), "=f"(v.z), "=f"(v.w) : "l"(p));
    return v;
}
// never-re-read output: streaming stores
DINLINE void stcs_f2(float* p, float2 v) {
    asm volatile("st.global.cs.v2.f32 [%0], {%1, %2};"
                 :: "l"(p), "f"(v.x), "f"(v.y) : "memory");
}

// ---------------------------------------------------------------------------
// chunk loads: A 1024 16B-chunks + B 1024 -> 8+8 per thread (128 threads)
// ---------------------------------------------------------------------------
DINLINE void load_chunk(uint32_t stage_base, int m_base, int n_base,
                        int kc, int tid) {
    const uint32_t astage = stage_base;
    const uint32_t bstage = stage_base + A_BYTES;
#pragma unroll
    for (int i = 0; i < 8; i++) {
        const int idx = i * THREADS + tid;  // [0, 1024)
        const int row = idx >> 3;
        const int c16 = idx & 7;
        const __half* g = g_Xh + (size_t)(m_base + row) * 256
                          + kc * K_CHUNK + c16 * 8;
        cp_async16(astage + SWZ(row * 128 + c16 * 16), g);
    }
#pragma unroll
    for (int i = 0; i < 8; i++) {
        const int idx = i * THREADS + tid;
        const int row = idx >> 3;
        const int c16 = idx & 7;
        const __half* g = g_Wh + (size_t)(n_base + row) * 256
                          + kc * K_CHUNK + c16 * 8;
        cp_async16(bstage + SWZ(row * 128 + c16 * 16), g);
    }
    CP_COMMIT();
}

// load all fragments for one k16 step into (a, b)
DINLINE void load_frags(uint32_t astage, uint32_t bstage,
                        int m_off, int n_off, int grp, int r8, int ks,
                        uint32_t a[4][4], uint32_t b[8][2]) {
#pragma unroll
    for (int mi = 0; mi < 4; mi++) {
        const int row = m_off + mi * 16 + (grp & 1) * 8 + r8;
        const int cg  = ks * 2 + (grp >> 1);
        ldsm_x4(a[mi][0], a[mi][1], a[mi][2], a[mi][3],
                astage + SWZ(row * 128 + cg * 16));
    }
#pragma unroll
    for (int p = 0; p < 4; p++) {
        const int row = n_off + p * 16 + (grp >> 1) * 8 + r8;
        const int cg  = ks * 2 + (grp & 1);
        ldsm_x4(b[2 * p][0], b[2 * p][1], b[2 * p + 1][0], b[2 * p + 1][1],
                bstage + SWZ(row * 128 + cg * 16));
    }
}

DINLINE void mma_all(float acc[4][8][4], uint32_t a[4][4], uint32_t b[8][2]) {
#pragma unroll
    for (int mi = 0; mi < 4; mi++)
#pragma unroll
        for (int ni = 0; ni < 8; ni++)
            mma16816(acc[mi][ni], a[mi], b[ni]);
}

// ---------------------------------------------------------------------------
// Fused kernel: [0,1024) W-prep | per mtile m: 8 X-prep then 16 gemm blocks.
// ---------------------------------------------------------------------------
__global__ void __launch_bounds__(THREADS, 2)
fused_kernel(const float* __restrict__ X,
             const float* __restrict__ W_exp,
             const float* __restrict__ b_exp,
             float* __restrict__ out) {
    const int blk = blockIdx.x;
    const int tid = threadIdx.x;

    // ======================= W-prep blocks =======================
    if (blk < NW_BLOCKS) {
        // covers n = 2*blk, 2*blk+1 (128 k-pairs each); 2 pairs per thread
#pragma unroll
        for (int h2 = 0; h2 < 2; h2++) {
            const int p = blk * 256 + h2 * 128 + tid;
            const int n = p >> 7;
            const int k = (p & 127) * 2;
            const int g = n >> 8, h = n & 255;
            const float* base = W_exp + ((size_t)(g * 8) * 256 + h) * 256 + k;
            float s0 = 0.f, s1 = 0.f;
#pragma unroll
            for (int e = 0; e < 8; e++) {
                float2 v = ldcs_f2(base + (size_t)e * 65536);
                s0 += v.x;
                s1 += v.y;
            }
            __half2 hv = __floats2half2_rn(s0, s1);
            *(uint32_t*)(g_Wh + (size_t)n * 256 + k) = *(uint32_t*)&hv;
        }
        if (tid < 2) {
            const int n = blk * 2 + tid;
            const int g = n >> 8, h = n & 255;
            float bs = 0.f;
#pragma unroll
            for (int e = 0; e < 8; e++)
                bs += b_exp[(g * 8 + e) * 256 + h];
            g_bsum[n] = bs;
        }
        __threadfence();
        __syncthreads();
        if (tid == 0) atomicAdd(&g_cnt[0], 1);
        return;
    }

    const int r = blk - NW_BLOCKS;
    const int m = r / GRP;
    const int q = r - m * GRP;

    // ======================= X-prep blocks =======================
    if (q < X_PER_M) {
        // xblk covers rows [16*xblk, 16*xblk+16): 1024 float4, 8 per thread
        const int xblk = m * X_PER_M + q;
        const size_t f4base = (size_t)xblk * 1024 + tid;
        const float4* src = (const float4*)X;
        float4 v[8];
#pragma unroll
        for (int j = 0; j < 8; j++)
            v[j] = ldcs_f4((const float*)(src + f4base + j * 128));
#pragma unroll
        for (int j = 0; j < 8; j++) {
            __half2 lo = __floats2half2_rn(v[j].x, v[j].y);
            __half2 hi = __floats2half2_rn(v[j].z, v[j].w);
            uint2 pk;
            pk.x = *(uint32_t*)&lo;
            pk.y = *(uint32_t*)&hi;
            *(uint2*)(g_Xh + (f4base + j * 128) * 4) = pk;
        }
        __threadfence();
        __syncthreads();
        if (tid == 0) atomicAdd(&g_cnt[1 + m], 1);
        return;
    }

    // ======================= GEMM blocks =======================
    const int ntile = q - X_PER_M;              // 0..15
    const int m_base = m * M_TILE;
    const int n_base = ntile * N_TILE;

    // wait for producers (all strictly earlier in the grid; prep never waits
    // -> forward progress guaranteed)
    if (tid == 0) {
        while (atomicAdd(&g_cnt[0], 0) < NW_BLOCKS) __nanosleep(128);
        while (atomicAdd(&g_cnt[1 + m], 0) < X_PER_M) __nanosleep(128);
        __threadfence();
    }
    __syncthreads();

    extern __shared__ char smem[];
    const uint32_t sbase = smem_u32(smem);
    const int wid = tid >> 5;
    const int lid = tid & 31;

    // bias slice
    *(float*)(smem + OFF_BIAS + tid * 4) = g_bsum[n_base + tid];

    // ---- prologue: fill 3 stages ----
    load_chunk(sbase + 0 * STAGE_BYTES, m_base, n_base, 0, tid);
    load_chunk(sbase + 1 * STAGE_BYTES, m_base, n_base, 1, tid);
    load_chunk(sbase + 2 * STAGE_BYTES, m_base, n_base, 2, tid);

    // warp tiling: 2 (m) x 2 (n) warps, warp tile 64x64
    const int warp_m = wid >> 1;
    const int warp_n = wid & 1;
    const int m_off = warp_m * 64;
    const int n_off = warp_n * 64;
    const int grp = lid >> 3;                   // 0..3
    const int r8  = lid & 7;

    float acc[4][8][4];
#pragma unroll
    for (int mi = 0; mi < 4; mi++)
#pragma unroll
        for (int ni = 0; ni < 8; ni++)
#pragma unroll
            for (int j = 0; j < 4; j++) acc[mi][ni][j] = 0.f;

    uint32_t abuf[2][4][4];
    uint32_t bbuf[2][8][2];

    // ---- main loop over K chunks (R13/R6 verbatim) ----
#pragma unroll
    for (int kc = 0; kc < NUM_CHUNKS; kc++) {
        if (kc == 0) CP_WAIT(2);
        else if (kc == 1) CP_WAIT(2);   // chunk3 refill may still be pending
        else if (kc == 2) CP_WAIT(1);
        else CP_WAIT(0);
        __syncthreads();

        const uint32_t astage = sbase + (kc % 3) * STAGE_BYTES;
        const uint32_t bstage = astage + A_BYTES;

        // prime k-step 0
        load_frags(astage, bstage, m_off, n_off, grp, r8, 0, abuf[0], bbuf[0]);

#pragma unroll
        for (int ks = 0; ks < 4; ks++) {
            const int cur = ks & 1, nxt = cur ^ 1;
            if (ks < 3)
                load_frags(astage, bstage, m_off, n_off, grp, r8, ks + 1,
                           abuf[nxt], bbuf[nxt]);
            mma_all(acc, abuf[cur], bbuf[cur]);
        }

        if (kc == 0) {
            // stage 0 fully consumed by all warps -> refill with chunk 3
            __syncthreads();
            load_chunk(sbase + 0 * STAGE_BYTES, m_base, n_base, 3, tid);
        }
    }

    // ---- epilogue: bias + streaming stores (output is never re-read) ----
    const float* sbias = (const float*)(smem + OFF_BIAS);
    const int qrow = lid >> 2;                  // 0..7
    const int qcol = (lid & 3) * 2;             // 0,2,4,6

#pragma unroll
    for (int mi = 0; mi < 4; mi++) {
        const int r0 = m_base + m_off + mi * 16 + qrow;
        float* orow0 = out + (size_t)r0 * NN + n_base;
        float* orow1 = orow0 + (size_t)8 * NN;
#pragma unroll
        for (int ni = 0; ni < 8; ni++) {
            const int col = n_off + ni * 8 + qcol;
            const float b0 = sbias[col], b1 = sbias[col + 1];
            stcs_f2(orow0 + col,
                    make_float2(acc[mi][ni][0] + b0, acc[mi][ni][1] + b1));
            stcs_f2(orow1 + col,
                    make_float2(acc[mi][ni][2] + b0, acc[mi][ni][3] + b1));
        }
    }
}

// ---------------------------------------------------------------------------
// Launch
// ---------------------------------------------------------------------------
extern "C" void kernel_launch(void* const* d_in, const int* in_sizes, int n_in,
                              void* d_out, int out_size) {
    const float* x     = (const float*)d_in[0];
    // d_in[1]=W_gate, d_in[2]=b_gate: softmax row-sum == 1 -> unused.
    const float* W_exp = (const float*)d_in[3];
    const float* b_exp = (const float*)d_in[4];
    float* out = (float*)d_out;

    cudaFuncSetAttribute(fused_kernel,
                         cudaFuncAttributeMaxDynamicSharedMemorySize, SMEM_TOTAL);

    // zero the producer->consumer counters (graph-capturable, deterministic)
    void* cnt_addr = nullptr;
    cudaGetSymbolAddress(&cnt_addr, g_cnt);
    cudaMemsetAsync(cnt_addr, 0, sizeof(int) * (1 + NUM_MTILES));

    fused_kernel<<<GRID_TOTAL, THREADS, SMEM_TOTAL>>>(x, W_exp, b_exp, out);
}

// round 17
// speedup vs baseline: 1.4221x; 1.4221x over previous
#include <cuda_runtime.h>
#include <cuda_fp16.h>
#include <cstdint>

// ============================================================================
// NestedMoEModel: softmax gate row-sums to 1 => gate path is a no-op.
// out[B, G*H] = x @ (sum_e W_exp)^T + sum_e b_exp
// Single GEMM M=32768, N=2048, K=256 via fp16 mma.sync (fp32 accumulate).
// PTX target is sm_103 (no 'a') -> tcgen05 unavailable; mma.sync path.
// R17 (final): R15 verbatim — session optimum (measured 106.9us).
//   gemm 97us: CTA 128x128, 128 thr, 2x2 warps of 64x64, 3-stage cp.async
//   ring, register fragment double-buffering, 2 CTAs/SM. Pinned at the legacy
//   mma.sync issue ceiling (~59% of tcgen05-normalized tensor peak, invariant
//   across 8 schedule families). prep ~9.9us: float2 W-reduce + MLP-8 xconv,
//   ld.global.cs on read-once sources. st.global.cs on never-re-read output.
//   R16's intra-kernel fusion regressed 42% (spinning consumers hold SM
//   residency slots) — reverted.
// ============================================================================

#define DINLINE __device__ __forceinline__

static constexpr int Bsz = 32768;
static constexpr int Dsz = 256;     // K
static constexpr int NN  = 2048;    // G*H = output cols
static constexpr int M_TILE = 128;
static constexpr int N_TILE = 128;
static constexpr int K_CHUNK = 64;                   // halves per chunk (128B rows)
static constexpr int NUM_CHUNKS = Dsz / K_CHUNK;     // 4
static constexpr int STAGES = 3;
static constexpr int THREADS = 128;                  // 4 warps, 2x2 grid of 64x64

// SMEM: 3 stages, each A(16KB)+B(16KB), + bias
static constexpr int A_BYTES = M_TILE * 128;         // 16384
static constexpr int B_BYTES = N_TILE * 128;         // 16384
static constexpr int STAGE_BYTES = A_BYTES + B_BYTES;    // 32768
static constexpr int OFF_BIAS = STAGES * STAGE_BYTES;    // 98304
static constexpr int SMEM_TOTAL = OFF_BIAS + N_TILE * 4; // 98816 -> 2 CTAs/SM

// Scratch (device globals: no allocations allowed)
__device__ __align__(128) __half g_Wh[NN * Dsz];     // 1MB  fp16 reduced weights
__device__ __align__(128) __half g_Xh[Bsz * Dsz];    // 16MB fp16 x
__device__ __align__(128) float  g_bsum[NN];

// ---------------------------------------------------------------------------
// helpers
// ---------------------------------------------------------------------------
DINLINE uint32_t smem_u32(const void* p) {
    uint32_t a;
    asm("{ .reg .u64 t; cvta.to.shared.u64 t, %1; cvt.u32.u64 %0, t; }"
        : "=r"(a) : "l"(p));
    return a;
}

DINLINE void cp_async16(uint32_t saddr, const void* gaddr) {
    asm volatile("cp.async.cg.shared.global [%0], [%1], 16;"
                 :: "r"(saddr), "l"(gaddr) : "memory");
}
#define CP_COMMIT() asm volatile("cp.async.commit_group;" ::: "memory")
#define CP_WAIT(n)  asm volatile("cp.async.wait_group %0;" :: "n"(n) : "memory")

// SW128-style XOR swizzle for 128B rows (16B granularity)
#define SWZ(o) ((o) ^ (((o) >> 3) & 0x70))

DINLINE void ldsm_x4(uint32_t& r0, uint32_t& r1, uint32_t& r2, uint32_t& r3,
                     uint32_t addr) {
    asm volatile("ldmatrix.sync.aligned.m8n8.x4.shared.b16 {%0,%1,%2,%3}, [%4];"
                 : "=r"(r0), "=r"(r1), "=r"(r2), "=r"(r3) : "r"(addr));
}

DINLINE void mma16816(float* d, const uint32_t* a, const uint32_t* b) {
    asm volatile(
        "mma.sync.aligned.m16n8k16.row.col.f32.f16.f16.f32 "
        "{%0,%1,%2,%3}, {%4,%5,%6,%7}, {%8,%9}, {%0,%1,%2,%3};"
        : "+f"(d[0]), "+f"(d[1]), "+f"(d[2]), "+f"(d[3])
        : "r"(a[0]), "r"(a[1]), "r"(a[2]), "r"(a[3]), "r"(b[0]), "r"(b[1]));
}

// read-once fp32 sources: streaming loads (evict-first in L2)
DINLINE float2 ldcs_f2(const float* p) {
    float2 v;
    asm("ld.global.cs.v2.f32 {%0, %1}, [%2];"
        : "=f"(v.x), "=f"(v.y) : "l"(p));
    return v;
}
DINLINE float4 ldcs_f4(const float* p) {
    float4 v;
    asm("ld.global.cs.v4.f32 {%0, %1, %2, %3}, [%4];"
        : "=f"(v.x), "=f"(v.y), "=f"(v.z), "=f"(v.w) : "l"(p));
    return v;
}
// never-re-read output: streaming stores
DINLINE void stcs_f2(float* p, float2 v) {
    asm volatile("st.global.cs.v2.f32 [%0], {%1, %2};"
                 :: "l"(p), "f"(v.x), "f"(v.y) : "memory");
}

// ---------------------------------------------------------------------------
// Fused prep:
//  blocks [0,1024):    W reduce over experts -> fp16 (float2 granularity,
//                      2 outputs/thread); blocks [0,8) also do bias sums.
//  blocks [1024,2048): x -> fp16, 8 independent float4 per thread (MLP 8).
// ---------------------------------------------------------------------------
__global__ void __launch_bounds__(256)
prep_kernel(const float* __restrict__ X,
            const float* __restrict__ W_exp,
            const float* __restrict__ b_exp) {
    const int blk = blockIdx.x;
    const int tid = threadIdx.x;

    if (blk < 1024) {
        // pair index p: n = p>>7, k = (p&127)*2
        const int p  = blk * 256 + tid;          // [0, 262144)
        const int n  = p >> 7;                   // 0..2047
        const int k  = (p & 127) * 2;
        const int g  = n >> 8, h = n & 255;
        const float* base = W_exp + ((size_t)(g * 8) * 256 + h) * 256 + k;
        float s0 = 0.f, s1 = 0.f;
#pragma unroll
        for (int e = 0; e < 8; e++) {
            float2 v = ldcs_f2(base + (size_t)e * 65536);
            s0 += v.x;
            s1 += v.y;
        }
        __half2 hv = __floats2half2_rn(s0, s1);
        *(uint32_t*)(g_Wh + (size_t)n * 256 + k) = *(uint32_t*)&hv;

        if (blk < 8) {
            float bs = 0.f;
#pragma unroll
            for (int e = 0; e < 8; e++)
                bs += b_exp[(blk * 8 + e) * 256 + tid];
            g_bsum[blk * 256 + tid] = bs;
        }
    } else {
        // each block: 256 threads x 8 float4 = 8192 floats (MLP = 8)
        const size_t f4base = (size_t)(blk - 1024) * 2048 + tid;
        const float4* src = (const float4*)X;
        float4 v[8];
#pragma unroll
        for (int j = 0; j < 8; j++)
            v[j] = ldcs_f4((const float*)(src + f4base + j * 256));
#pragma unroll
        for (int j = 0; j < 8; j++) {
            __half2 lo = __floats2half2_rn(v[j].x, v[j].y);
            __half2 hi = __floats2half2_rn(v[j].z, v[j].w);
            uint2 pk;
            pk.x = *(uint32_t*)&lo;
            pk.y = *(uint32_t*)&hi;
            *(uint2*)(g_Xh + (f4base + j * 256) * 4) = pk;
        }
    }
}
static constexpr int PREP_BLOCKS = 1024 + (Bsz * Dsz) / (256 * 32);   // 2048

// ---------------------------------------------------------------------------
// chunk loads: A 1024 16B-chunks + B 1024 -> 8+8 per thread (128 threads)
// ---------------------------------------------------------------------------
DINLINE void load_chunk(uint32_t stage_base, int m_base, int n_base,
                        int kc, int tid) {
    const uint32_t astage = stage_base;
    const uint32_t bstage = stage_base + A_BYTES;
#pragma unroll
    for (int i = 0; i < 8; i++) {
        const int idx = i * THREADS + tid;  // [0, 1024)
        const int row = idx >> 3;
        const int c16 = idx & 7;
        const __half* g = g_Xh + (size_t)(m_base + row) * 256
                          + kc * K_CHUNK + c16 * 8;
        cp_async16(astage + SWZ(row * 128 + c16 * 16), g);
    }
#pragma unroll
    for (int i = 0; i < 8; i++) {
        const int idx = i * THREADS + tid;
        const int row = idx >> 3;
        const int c16 = idx & 7;
        const __half* g = g_Wh + (size_t)(n_base + row) * 256
                          + kc * K_CHUNK + c16 * 8;
        cp_async16(bstage + SWZ(row * 128 + c16 * 16), g);
    }
    CP_COMMIT();
}

// load all fragments for one k16 step into (a, b)
DINLINE void load_frags(uint32_t astage, uint32_t bstage,
                        int m_off, int n_off, int grp, int r8, int ks,
                        uint32_t a[4][4], uint32_t b[8][2]) {
#pragma unroll
    for (int mi = 0; mi < 4; mi++) {
        const int row = m_off + mi * 16 + (grp & 1) * 8 + r8;
        const int cg  = ks * 2 + (grp >> 1);
        ldsm_x4(a[mi][0], a[mi][1], a[mi][2], a[mi][3],
                astage + SWZ(row * 128 + cg * 16));
    }
#pragma unroll
    for (int p = 0; p < 4; p++) {
        const int row = n_off + p * 16 + (grp >> 1) * 8 + r8;
        const int cg  = ks * 2 + (grp & 1);
        ldsm_x4(b[2 * p][0], b[2 * p][1], b[2 * p + 1][0], b[2 * p + 1][1],
                bstage + SWZ(row * 128 + cg * 16));
    }
}

DINLINE void mma_all(float acc[4][8][4], uint32_t a[4][4], uint32_t b[8][2]) {
#pragma unroll
    for (int mi = 0; mi < 4; mi++)
#pragma unroll
        for (int ni = 0; ni < 8; ni++)
            mma16816(acc[mi][ni], a[mi], b[ni]);
}

// ---------------------------------------------------------------------------
// GEMM: out = Xh @ Wh^T + bsum
// CTA 128x128, 128 threads (4 warps, 2x2 grid, warp tile 64x64). 2 CTAs/SM.
// 3-stage cp.async pipeline, register fragment double-buffering.
// ---------------------------------------------------------------------------
__global__ void __launch_bounds__(THREADS, 2)
gemm_kernel(float* __restrict__ out) {
    extern __shared__ char smem[];
    const uint32_t sbase = smem_u32(smem);
    const int tid = threadIdx.x;
    const int wid = tid >> 5;
    const int lid = tid & 31;

    // 16 consecutive CTAs share one A tile (L2 locality on A)
    const int mtile = blockIdx.x >> 4;          // 0..255
    const int ntile = blockIdx.x & 15;          // 0..15
    const int m_base = mtile * M_TILE;
    const int n_base = ntile * N_TILE;

    // bias slice
    *(float*)(smem + OFF_BIAS + tid * 4) = g_bsum[n_base + tid];

    // ---- prologue: fill 3 stages ----
    load_chunk(sbase + 0 * STAGE_BYTES, m_base, n_base, 0, tid);
    load_chunk(sbase + 1 * STAGE_BYTES, m_base, n_base, 1, tid);
    load_chunk(sbase + 2 * STAGE_BYTES, m_base, n_base, 2, tid);

    // warp tiling: 2 (m) x 2 (n) warps, warp tile 64x64
    const int warp_m = wid >> 1;
    const int warp_n = wid & 1;
    const int m_off = warp_m * 64;
    const int n_off = warp_n * 64;
    const int grp = lid >> 3;                   // 0..3
    const int r8  = lid & 7;

    float acc[4][8][4];
#pragma unroll
    for (int mi = 0; mi < 4; mi++)
#pragma unroll
        for (int ni = 0; ni < 8; ni++)
#pragma unroll
            for (int j = 0; j < 4; j++) acc[mi][ni][j] = 0.f;

    uint32_t abuf[2][4][4];
    uint32_t bbuf[2][8][2];

    // ---- main loop over K chunks ----
#pragma unroll
    for (int kc = 0; kc < NUM_CHUNKS; kc++) {
        if (kc == 0) CP_WAIT(2);
        else if (kc == 1) CP_WAIT(2);   // chunk3 refill may still be pending
        else if (kc == 2) CP_WAIT(1);
        else CP_WAIT(0);
        __syncthreads();

        const uint32_t astage = sbase + (kc % 3) * STAGE_BYTES;
        const uint32_t bstage = astage + A_BYTES;

        // prime k-step 0
        load_frags(astage, bstage, m_off, n_off, grp, r8, 0, abuf[0], bbuf[0]);

#pragma unroll
        for (int ks = 0; ks < 4; ks++) {
            const int cur = ks & 1, nxt = cur ^ 1;
            if (ks < 3)
                load_frags(astage, bstage, m_off, n_off, grp, r8, ks + 1,
                           abuf[nxt], bbuf[nxt]);
            mma_all(acc, abuf[cur], bbuf[cur]);
        }

        if (kc == 0) {
            // stage 0 fully consumed by all warps -> refill with chunk 3
            __syncthreads();
            load_chunk(sbase + 0 * STAGE_BYTES, m_base, n_base, 3, tid);
        }
    }

    // ---- epilogue: bias + streaming stores (output is never re-read) ----
    const float* sbias = (const float*)(smem + OFF_BIAS);
    const int qrow = lid >> 2;                  // 0..7
    const int qcol = (lid & 3) * 2;             // 0,2,4,6

#pragma unroll
    for (int mi = 0; mi < 4; mi++) {
        const int r0 = m_base + m_off + mi * 16 + qrow;
        float* orow0 = out + (size_t)r0 * NN + n_base;
        float* orow1 = orow0 + (size_t)8 * NN;
#pragma unroll
        for (int ni = 0; ni < 8; ni++) {
            const int col = n_off + ni * 8 + qcol;
            const float b0 = sbias[col], b1 = sbias[col + 1];
            stcs_f2(orow0 + col,
                    make_float2(acc[mi][ni][0] + b0, acc[mi][ni][1] + b1));
            stcs_f2(orow1 + col,
                    make_float2(acc[mi][ni][2] + b0, acc[mi][ni][3] + b1));
        }
    }
}

// ---------------------------------------------------------------------------
// Launch
// ---------------------------------------------------------------------------
extern "C" void kernel_launch(void* const* d_in, const int* in_sizes, int n_in,
                              void* d_out, int out_size) {
    const float* x     = (const float*)d_in[0];
    // d_in[1]=W_gate, d_in[2]=b_gate: softmax row-sum == 1 -> unused.
    const float* W_exp = (const float*)d_in[3];
    const float* b_exp = (const float*)d_in[4];
    float* out = (float*)d_out;

    cudaFuncSetAttribute(gemm_kernel,
                         cudaFuncAttributeMaxDynamicSharedMemorySize, SMEM_TOTAL);

    prep_kernel<<<PREP_BLOCKS, 256>>>(x, W_exp, b_exp);
    gemm_kernel<<<(Bsz / M_TILE) * (NN / N_TILE), THREADS, SMEM_TOTAL>>>(out);
}